// round 7
// baseline (speedup 1.0000x reference)
#include <cuda_runtime.h>
#include <cstdint>

// Shapes (fixed by the problem)
#define B_    4
#define CIN   64
#define COUT  64
#define H_    512
#define W_    512
#define WDIM  512
#define TAPS  9
#define CC    4            // cins per pipeline chunk
#define NCHUNK (CIN/CC)    // 16
#define TW    256          // output tile width per block
#define SX_ROW 264         // staged floats per x row: gcol in [colbase-4, colbase+260)
#define SX_BUF (CC*3*SX_ROW)   // 3168 floats
#define SW_BUF (CC*TAPS*COUT)  // 2304 floats

// Folded per-batch weights: [b][cin][tap][cout]
__device__ float g_w[B_ * CIN * TAPS * COUT];

// ---------------------------------------------------------------------------
// helpers
// ---------------------------------------------------------------------------
__device__ __forceinline__ unsigned long long f2_fma(unsigned long long a,
                                                     unsigned long long b,
                                                     unsigned long long c) {
    unsigned long long d;
    asm("fma.rn.f32x2 %0, %1, %2, %3;" : "=l"(d) : "l"(a), "l"(b), "l"(c));
    return d;
}
__device__ __forceinline__ unsigned long long f2_dup(float v) {
    unsigned long long d;
    asm("mov.b64 %0, {%1, %1};" : "=l"(d) : "f"(v));
    return d;
}
__device__ __forceinline__ void f2_unpack(unsigned long long p, float& lo, float& hi) {
    asm("mov.b64 {%0, %1}, %2;" : "=f"(lo), "=f"(hi) : "l"(p));
}
// 16B-granule XOR swizzle: flip bit4 based on bit7 (conflict-free for the
// 32B-strided per-lane access pattern below). Applied identically on the
// cp.async store side and the LDS side; preserves 16B alignment.
__device__ __forceinline__ uint32_t swz(uint32_t a) { return a ^ ((a >> 3) & 16u); }

__device__ __forceinline__ void cp16(uint32_t dst, const float* src, bool pred) {
    int sz = pred ? 16 : 0;
    asm volatile("cp.async.cg.shared.global [%0], [%1], 16, %2;"
                 :: "r"(dst), "l"(src), "r"(sz));
}
__device__ __forceinline__ void cp_commit() { asm volatile("cp.async.commit_group;"); }
__device__ __forceinline__ void cp_wait0()  { asm volatile("cp.async.wait_group 0;"); }

__device__ __forceinline__ float4 lds128(uint32_t a) {
    float4 v;
    asm volatile("ld.shared.v4.f32 {%0,%1,%2,%3}, [%4];"
                 : "=f"(v.x), "=f"(v.y), "=f"(v.z), "=f"(v.w) : "r"(a));
    return v;
}
__device__ __forceinline__ float lds32(uint32_t a) {
    float v;
    asm volatile("ld.shared.f32 %0, [%1];" : "=f"(v) : "r"(a));
    return v;
}
__device__ __forceinline__ unsigned long long lds64(uint32_t a) {
    unsigned long long v;
    asm volatile("ld.shared.b64 %0, [%1];" : "=l"(v) : "r"(a));
    return v;
}

// ---------------------------------------------------------------------------
// Phase 1: style / demod / fold weights into g_w[b][cin][tap][cout]
// conv_w layout: [kh][kw][cin][cout]
// ---------------------------------------------------------------------------
__global__ void prep_kernel(const float* __restrict__ w,
                            const float* __restrict__ conv_w,
                            const float* __restrict__ mod_w,
                            const float* __restrict__ mod_b) {
    __shared__ float s_style[CIN];
    __shared__ float s_d[COUT];
    const int b   = blockIdx.x;
    const int tid = threadIdx.x;
    const float rc_dense = 0.04419417382415922f;  // 1/sqrt(512)
    const float rc_conv  = 1.0f / 24.0f;          // 1/sqrt(3*3*64)

    if (tid < CIN) {
        float s = 0.f;
        const float* wb = w + b * WDIM;
        #pragma unroll 8
        for (int d = 0; d < WDIM; ++d)
            s += wb[d] * mod_w[d * CIN + tid];
        s_style[tid] = s * rc_dense + mod_b[tid] + 1.0f;
    }
    __syncthreads();

    if (tid < COUT) {
        float ss = 0.f;
        for (int cin = 0; cin < CIN; ++cin) {
            float st = rc_conv * s_style[cin];
            #pragma unroll
            for (int tap = 0; tap < TAPS; ++tap) {
                float v = conv_w[(tap * CIN + cin) * COUT + tid] * st;
                ss += v * v;
            }
        }
        s_d[tid] = rsqrtf(ss + 1e-8f);
    }
    __syncthreads();

    float* gw = g_w + b * CIN * TAPS * COUT;
    for (int idx = tid; idx < CIN * TAPS * COUT; idx += blockDim.x) {
        int cout = idx & (COUT - 1);
        int tap  = (idx >> 6) % TAPS;
        int cin  = idx / (TAPS * COUT);
        gw[idx] = rc_conv * conv_w[(tap * CIN + cin) * COUT + cout]
                * s_style[cin] * s_d[cout];
    }
}

// ---------------------------------------------------------------------------
// Phase 2: direct 3x3 SAME conv, grouped by batch.
// Block: 256 threads = 8 warps; warp = one cout-group of 8 couts over all
// TW=256 pixels of one row. Thread: 8 CONSECUTIVE pixels x 4 cout-pairs
// (FFMA2 packs cout pairs) -> 32 f32x2 accumulators.
// x per (cin,kh): 10-float sliding window = 2xLDS.128 + 2xLDS.32 (swizzled,
// conflict-free). w: broadcast LDS.64 per (tap, cout-pair).
// cp.async double-buffered staging, one bar.sync per chunk.
// ---------------------------------------------------------------------------
__global__ void __launch_bounds__(256, 2)
conv_kernel(const float* __restrict__ x, float* __restrict__ out) {
    __shared__ __align__(16) float sxs[2][SX_BUF];
    __shared__ __align__(16) float sws[2][SW_BUF];

    const int tid     = threadIdx.x;
    const int lane    = tid & 31;
    const int cg      = tid >> 5;          // cout group (warp id)
    const int colbase = blockIdx.x * TW;
    const int row     = blockIdx.y;
    const int b       = blockIdx.z;

    const float* xb = x + (size_t)b * CIN * H_ * W_;
    const float* gw = g_w + b * CIN * TAPS * COUT;

    const uint32_t sx_base = (uint32_t)__cvta_generic_to_shared(&sxs[0][0]);
    const uint32_t sw_base = (uint32_t)__cvta_generic_to_shared(&sws[0][0]);

    unsigned long long acc[4][8];          // [cout-pair][pixel]
    #pragma unroll
    for (int p = 0; p < 4; ++p)
        #pragma unroll
        for (int j = 0; j < 8; ++j) acc[p][j] = 0ull;

    // --- staging: one CC-cin chunk into buffer buf ---
    auto stage = [&](int chunk, int buf) {
        const uint32_t sxb = sx_base + (uint32_t)buf * (SX_BUF * 4);
        const uint32_t swb = sw_base + (uint32_t)buf * (SW_BUF * 4);
        const int c0 = chunk * CC;
        // x: CC cin x 3 rows x 66 16B-chunks, zero-filled at borders
        for (int idx = tid; idx < CC * 3 * 66; idx += 256) {
            int c16 = idx % 66;
            int t   = idx / 66;
            int kh  = t % 3;
            int cc  = t / 3;
            int grow = row + kh - 1;
            int g0   = colbase - 4 + c16 * 4;
            bool ok  = ((unsigned)grow < (unsigned)H_) &&
                       ((unsigned)g0   < (unsigned)(W_ - 3));
            int sgr = ((unsigned)grow < (unsigned)H_) ? grow : 0;
            int sg0 = ok ? g0 : 0;
            const float* src = xb + ((size_t)(c0 + cc) * H_ + sgr) * W_ + sg0;
            uint32_t dst = swz(sxb + (uint32_t)(((cc * 3 + kh) * SX_ROW + c16 * 4) * 4));
            cp16(dst, src, ok);
        }
        // w: contiguous [cin][tap][cout]
        const float* wsrc = gw + c0 * TAPS * COUT;
        for (int idx = tid; idx < SW_BUF / 4; idx += 256)
            cp16(swb + (uint32_t)(idx * 16), wsrc + idx * 4, true);
    };

    stage(0, 0);
    cp_commit();

    for (int c = 0; c < NCHUNK; ++c) {
        cp_wait0();
        __syncthreads();                   // chunk c staged & visible; buf c^1 free
        if (c + 1 < NCHUNK) stage(c + 1, (c + 1) & 1);
        cp_commit();

        const int buf = c & 1;
        const uint32_t sxb = sx_base + (uint32_t)buf * (SX_BUF * 4);
        const uint32_t swb = sw_base + (uint32_t)buf * (SW_BUF * 4);

        #pragma unroll
        for (int cc = 0; cc < CC; ++cc) {
            #pragma unroll
            for (int kh = 0; kh < 3; ++kh) {
                // 10-float window: ci = 3+8*lane .. 12+8*lane
                uint32_t rb = sxb + (uint32_t)(((cc * 3 + kh) * SX_ROW) * 4) + lane * 32;
                float  s0 = lds32 (swz(rb + 12));
                float4 va = lds128(swz(rb + 16));
                float4 vb = lds128(swz(rb + 32));
                float  s1 = lds32 (swz(rb + 48));
                unsigned long long xx[10];
                xx[0] = f2_dup(s0);
                xx[1] = f2_dup(va.x); xx[2] = f2_dup(va.y);
                xx[3] = f2_dup(va.z); xx[4] = f2_dup(va.w);
                xx[5] = f2_dup(vb.x); xx[6] = f2_dup(vb.y);
                xx[7] = f2_dup(vb.z); xx[8] = f2_dup(vb.w);
                xx[9] = f2_dup(s1);

                #pragma unroll
                for (int p = 0; p < 4; ++p) {
                    uint32_t wb = swb + (uint32_t)((((cc * 9 + kh * 3) * COUT)
                                                   + cg * 8 + 2 * p) * 4);
                    unsigned long long w0 = lds64(wb);              // kw=0, broadcast
                    unsigned long long w1 = lds64(wb + COUT * 4);   // kw=1
                    unsigned long long w2 = lds64(wb + 2 * COUT * 4);
                    #pragma unroll
                    for (int j = 0; j < 8; ++j) {
                        acc[p][j] = f2_fma(xx[j],     w0, acc[p][j]);
                        acc[p][j] = f2_fma(xx[j + 1], w1, acc[p][j]);
                        acc[p][j] = f2_fma(xx[j + 2], w2, acc[p][j]);
                    }
                }
            }
        }
    }

    // --- epilogue: out[b][cout][row][col], STG.128, px consecutive per thread ---
    size_t obase = ((size_t)b * COUT) * H_ * W_ + (size_t)row * W_
                 + colbase + lane * 8;
    #pragma unroll
    for (int p = 0; p < 4; ++p) {
        int cout0 = cg * 8 + 2 * p;
        float* o0 = out + obase + (size_t)cout0 * (H_ * W_);
        float* o1 = o0 + (size_t)(H_ * W_);
        float lo[8], hi[8];
        #pragma unroll
        for (int j = 0; j < 8; ++j) f2_unpack(acc[p][j], lo[j], hi[j]);
        reinterpret_cast<float4*>(o0)[0] = make_float4(lo[0], lo[1], lo[2], lo[3]);
        reinterpret_cast<float4*>(o0)[1] = make_float4(lo[4], lo[5], lo[6], lo[7]);
        reinterpret_cast<float4*>(o1)[0] = make_float4(hi[0], hi[1], hi[2], hi[3]);
        reinterpret_cast<float4*>(o1)[1] = make_float4(hi[4], hi[5], hi[6], hi[7]);
    }
}

// ---------------------------------------------------------------------------
// Harness entry. Inputs (metadata order): x, w, conv_w, mod_w, mod_b.
// ---------------------------------------------------------------------------
extern "C" void kernel_launch(void* const* d_in, const int* in_sizes, int n_in,
                              void* d_out, int out_size) {
    const float* x      = (const float*)d_in[0];
    const float* w      = (const float*)d_in[1];
    const float* conv_w = (const float*)d_in[2];
    const float* mod_w  = (const float*)d_in[3];
    const float* mod_b  = (const float*)d_in[4];
    float* out = (float*)d_out;

    prep_kernel<<<B_, 256>>>(w, conv_w, mod_w, mod_b);
    conv_kernel<<<dim3(W_ / TW, H_, B_), 256>>>(x, out);
    (void)in_sizes; (void)n_in; (void)out_size;
}

// round 13
// speedup vs baseline: 2.8568x; 2.8568x over previous
#include <cuda_runtime.h>
#include <cuda_bf16.h>
#include <cstdint>

// ---------------------------------------------------------------------------
// Shapes (fixed)
// ---------------------------------------------------------------------------
#define B_    4
#define CIN   64
#define COUT  64
#define H_    512
#define W_    512
#define WDIM  512
#define HW    (H_ * W_)

#define TW     256                // output px per tile (M)
#define PXBUF  272                // staged px per chunk: [colbase-8, colbase+264)
#define COMPBYTES (PXBUF * 128)   // 34816 B per comp (128B per px row, swizzled)
#define BUFBYTES  (2 * COMPBYTES) // 69632 per buffer
#define SMEM_TOTAL (2 * BUFBYTES) // 139264 B

// x split bf16, transposed: [b][comp][h][w][cin]
__device__ __align__(16) __nv_bfloat16 g_xs[(size_t)B_ * 2 * HW * CIN];
// W fragments, per b: 18 slices (tap*2+comp) x 2048 u32 in HMMA-lane order
__device__ __align__(16) uint32_t g_wB[B_][18 * 2048];

// ---------------------------------------------------------------------------
// helpers
// ---------------------------------------------------------------------------
__device__ __forceinline__ uint32_t smem_u32(const void* p) {
    return (uint32_t)__cvta_generic_to_shared(p);
}
__device__ __forceinline__ void cp16(uint32_t dst, const void* src, bool pred) {
    int sz = pred ? 16 : 0;
    asm volatile("cp.async.cg.shared.global [%0], [%1], 16, %2;"
                 :: "r"(dst), "l"(src), "r"(sz));
}
__device__ __forceinline__ void cp_commit() { asm volatile("cp.async.commit_group;"); }
__device__ __forceinline__ void cp_wait0()  { asm volatile("cp.async.wait_group 0;"); }

__device__ __forceinline__ void ldsm_x4(uint32_t* r, uint32_t addr) {
    asm volatile("ldmatrix.sync.aligned.m8n8.x4.shared.b16 {%0,%1,%2,%3}, [%4];"
                 : "=r"(r[0]), "=r"(r[1]), "=r"(r[2]), "=r"(r[3]) : "r"(addr));
}
__device__ __forceinline__ void mma16816(float* c, const uint32_t* a, const uint2 b) {
    asm volatile("mma.sync.aligned.m16n8k16.row.col.f32.bf16.bf16.f32 "
                 "{%0,%1,%2,%3}, {%4,%5,%6,%7}, {%8,%9}, {%0,%1,%2,%3};"
                 : "+f"(c[0]), "+f"(c[1]), "+f"(c[2]), "+f"(c[3])
                 : "r"(a[0]), "r"(a[1]), "r"(a[2]), "r"(a[3]),
                   "r"(b.x), "r"(b.y));
}

// ---------------------------------------------------------------------------
// Pre-pass: split x fp32 -> {hi, lo} bf16, transposed to [b][comp][h][w][cin].
// Grid (4 wchunks, 512 h, 4 b), 256 threads. smem-tiled transpose.
// ---------------------------------------------------------------------------
__global__ void xsplit_kernel(const float* __restrict__ x) {
    __shared__ float s[64][132];
    const int tid = threadIdx.x;
    const int wc = blockIdx.x, h = blockIdx.y, b = blockIdx.z;

    // load tile [64 cin][128 w] via float4 (coalesced)
    for (int i = tid; i < 2048; i += 256) {
        int cin = i >> 5, w4 = i & 31;
        float4 v = *(const float4*)(x + ((size_t)(b * 64 + cin) * HW)
                                     + h * 512 + wc * 128 + w4 * 4);
        s[cin][w4 * 4 + 0] = v.x; s[cin][w4 * 4 + 1] = v.y;
        s[cin][w4 * 4 + 2] = v.z; s[cin][w4 * 4 + 3] = v.w;
    }
    __syncthreads();

    // write [w][cin] bf16, per comp, uint4 (8 cins) at a time
    for (int i = tid; i < 2048; i += 256) {
        int w = i >> 4, comp = (i >> 3) & 1, cg = i & 7;
        uint32_t pk[4];
        #pragma unroll
        for (int j = 0; j < 4; ++j) {
            float v0 = s[cg * 8 + 2 * j][w], v1 = s[cg * 8 + 2 * j + 1][w];
            __nv_bfloat16 h0 = __float2bfloat16(v0);
            __nv_bfloat16 h1 = __float2bfloat16(v1);
            if (comp) {
                h0 = __float2bfloat16(v0 - __bfloat162float(h0));
                h1 = __float2bfloat16(v1 - __bfloat162float(h1));
            }
            pk[j] = (uint32_t)__bfloat16_as_ushort(h0)
                  | ((uint32_t)__bfloat16_as_ushort(h1) << 16);
        }
        uint4* dst = (uint4*)(g_xs + (((size_t)(b * 2 + comp) * HW
                                       + h * 512 + wc * 128 + w) * 64 + cg * 8));
        *dst = make_uint4(pk[0], pk[1], pk[2], pk[3]);
    }
}

// ---------------------------------------------------------------------------
// prep: style/demod, then write folded split-bf16 weights in per-lane HMMA
// B-fragment order: word idx = (((tap*2+comp)*8+gna)*4+kstep)*64 + lane*2 + reg.
// B frag (m16n8k16, col-major): b0=B[k0][n], b1=B[k0+1][n] (reg0);
// b2=B[k0+8][n], b3=B[k0+9][n] (reg1); k0=2*(lane&3)+kstep*16, n=gna*8+(lane>>2).
// conv_w layout [kh][kw][cin][cout]; B element (n=cout, k=cin).
// ---------------------------------------------------------------------------
__global__ void prep_kernel(const float* __restrict__ w,
                            const float* __restrict__ conv_w,
                            const float* __restrict__ mod_w,
                            const float* __restrict__ mod_b) {
    __shared__ float s_style[CIN];
    __shared__ float s_d[COUT];
    const int b   = blockIdx.x;
    const int tid = threadIdx.x;
    const float rc_dense = 0.04419417382415922f;  // 1/sqrt(512)
    const float rc_conv  = 1.0f / 24.0f;          // 1/sqrt(3*3*64)

    if (tid < CIN) {
        float s = 0.f;
        const float* wb = w + b * WDIM;
        #pragma unroll 8
        for (int d = 0; d < WDIM; ++d)
            s += wb[d] * mod_w[d * CIN + tid];
        s_style[tid] = s * rc_dense + mod_b[tid] + 1.0f;
    }
    __syncthreads();

    if (tid < COUT) {
        float ss = 0.f;
        for (int cin = 0; cin < CIN; ++cin) {
            float st = rc_conv * s_style[cin];
            #pragma unroll
            for (int tap = 0; tap < 9; ++tap) {
                float v = conv_w[(tap * CIN + cin) * COUT + tid] * st;
                ss += v * v;
            }
        }
        s_d[tid] = rsqrtf(ss + 1e-8f);
    }
    __syncthreads();

    uint32_t* dst = g_wB[b];
    for (int idx = tid; idx < 18 * 2048; idx += 256) {
        int slice = idx >> 11;           // tap*2 + comp
        int rem   = idx & 2047;
        int gna   = rem >> 8;            // 0..7
        int kstep = (rem >> 6) & 3;
        int lane  = (rem >> 1) & 31;
        int reg   = rem & 1;
        int tap = slice >> 1, comp = slice & 1;
        int n  = gna * 8 + (lane >> 2);
        int k0 = kstep * 16 + 2 * (lane & 3) + reg * 8;
        uint32_t word = 0;
        #pragma unroll
        for (int hh = 0; hh < 2; ++hh) {
            int k = k0 + hh;
            float wv = rc_conv * conv_w[(tap * CIN + k) * COUT + n]
                     * s_style[k] * s_d[n];
            __nv_bfloat16 hi = __float2bfloat16(wv);
            __nv_bfloat16 o  = comp ? __float2bfloat16(wv - __bfloat162float(hi))
                                    : hi;
            word |= (uint32_t)__bfloat16_as_ushort(o) << (16 * hh);
        }
        dst[idx] = word;
    }
}

// ---------------------------------------------------------------------------
// conv: split-bf16 implicit GEMM via mma.sync m16n8k16 (HMMA).
// Block: 256 thr = 8 warps = 4(M) x 2(N); tile 256px x 64cout; warp 64px x 32cout.
// Per tile: 3 kh chunks (double-buffered cp.async staging of [px 272][cin 64]
// bf16 x 2 comps, 16B-granule XOR swizzle). Per chunk: kw(3) x kstep(4):
// A = ldmatrix.x4 (hi & lo), B = lane-ordered LDG.64 fragments (hi & lo);
// products hh + lh + hl accumulated in 64 f32 regs.
// ---------------------------------------------------------------------------
__global__ void __launch_bounds__(256, 1)
conv_mma_kernel(float* __restrict__ out) {
    extern __shared__ char smem[];
    const uint32_t sxb0 = smem_u32(smem);
    const int tid  = threadIdx.x;
    const int lane = tid & 31;
    const int wid  = tid >> 5;
    const int warp_m = wid & 3;          // M offset = warp_m*64
    const int wn     = wid >> 2;         // N offset = wn*32
    const int colbase = blockIdx.x * TW;
    const int row     = blockIdx.y;
    const int b       = blockIdx.z;

    float acc[4][4][4];                  // [matom][natom][reg]
    #pragma unroll
    for (int i = 0; i < 4; ++i)
        #pragma unroll
        for (int j = 0; j < 4; ++j)
            #pragma unroll
            for (int r = 0; r < 4; ++r) acc[i][j][r] = 0.f;

    // staging: chunk c (kh=c) into buffer bf
    auto stage = [&](int c, int bf) {
        int ir = row + c - 1;
        for (int idx = tid; idx < 2 * PXBUF * 8; idx += 256) {
            int g    = idx & 7;
            int px   = (idx >> 3) % PXBUF;
            int comp = idx / (PXBUF * 8);
            int gpx  = colbase - 8 + px;
            bool ok  = ((unsigned)ir < (unsigned)H_) &&
                       ((unsigned)gpx < (unsigned)W_);
            const __nv_bfloat16* src =
                g_xs + ((size_t)(b * 2 + comp) * HW
                        + (ok ? (ir * 512 + gpx) : 0)) * 64 + g * 8;
            uint32_t dst = sxb0 + (uint32_t)bf * BUFBYTES
                         + (uint32_t)comp * COMPBYTES
                         + (uint32_t)px * 128 + (uint32_t)((g ^ (px & 7)) * 16);
            cp16(dst, src, ok);
        }
    };

    stage(0, 0);
    cp_commit();

    // lane-dependent A-address pieces (constant across loop)
    const int pxe   = ((lane >> 3) & 1) * 8 + (lane & 7);  // intra-mat px part
    const int kge   = (lane >> 4);                         // k-granule part

    for (int c = 0; c < 3; ++c) {
        cp_wait0();
        __syncthreads();
        if (c < 2) { stage(c + 1, (c + 1) & 1); cp_commit(); }

        const uint32_t sxb = sxb0 + (uint32_t)(c & 1) * BUFBYTES;
        const int kh = c;

        #pragma unroll
        for (int kw = 0; kw < 3; ++kw) {
            const uint32_t* ws = g_wB[b] + ((kh * 3 + kw) * 2) * 2048;
            #pragma unroll
            for (int kstep = 0; kstep < 4; ++kstep) {
                // ---- A fragments (hi, lo) via ldmatrix.x4 ----
                uint32_t ahi[4][4], alo[4][4];
                #pragma unroll
                for (int m = 0; m < 4; ++m) {
                    int pxb = warp_m * 64 + m * 16 + pxe + 7 + kw;
                    uint32_t sg = (uint32_t)((kstep * 2 + kge) ^ (pxb & 7));
                    uint32_t a0 = sxb + (uint32_t)pxb * 128 + sg * 16;
                    ldsm_x4(ahi[m], a0);
                    ldsm_x4(alo[m], a0 + COMPBYTES);
                }
                // ---- B fragments (hi, lo) lane-ordered LDG.64 ----
                uint2 bhi[4], blo[4];
                #pragma unroll
                for (int na = 0; na < 4; ++na) {
                    const uint32_t off =
                        (uint32_t)(((wn * 4 + na) * 4 + kstep) * 64 + lane * 2);
                    bhi[na] = *(const uint2*)(ws + off);
                    blo[na] = *(const uint2*)(ws + 2048 + off);
                }
                // ---- hh + lh + hl ----
                #pragma unroll
                for (int m = 0; m < 4; ++m)
                    #pragma unroll
                    for (int na = 0; na < 4; ++na) {
                        mma16816(acc[m][na], ahi[m], bhi[na]);
                        mma16816(acc[m][na], alo[m], bhi[na]);
                        mma16816(acc[m][na], ahi[m], blo[na]);
                    }
            }
        }
        __syncthreads();
    }

    // ---- epilogue: out[b][cout][row][col] ----
    #pragma unroll
    for (int m = 0; m < 4; ++m) {
        int px = colbase + warp_m * 64 + m * 16 + (lane >> 2);
        #pragma unroll
        for (int na = 0; na < 4; ++na) {
            int cout = wn * 32 + na * 8 + 2 * (lane & 3);
            float* o = out + ((size_t)(b * COUT + cout)) * HW
                     + (size_t)row * W_ + px;
            o[0]      = acc[m][na][0];   // (px,   cout)
            o[HW]     = acc[m][na][1];   // (px,   cout+1)
            o[8]      = acc[m][na][2];   // (px+8, cout)
            o[HW + 8] = acc[m][na][3];   // (px+8, cout+1)
        }
    }
}

// ---------------------------------------------------------------------------
// Harness entry. Inputs (metadata order): x, w, conv_w, mod_w, mod_b.
// ---------------------------------------------------------------------------
extern "C" void kernel_launch(void* const* d_in, const int* in_sizes, int n_in,
                              void* d_out, int out_size) {
    const float* x      = (const float*)d_in[0];
    const float* w      = (const float*)d_in[1];
    const float* conv_w = (const float*)d_in[2];
    const float* mod_w  = (const float*)d_in[3];
    const float* mod_b  = (const float*)d_in[4];
    float* out = (float*)d_out;

    cudaFuncSetAttribute(conv_mma_kernel,
                         cudaFuncAttributeMaxDynamicSharedMemorySize, SMEM_TOTAL);
    xsplit_kernel<<<dim3(4, 512, B_), 256>>>(x);
    prep_kernel<<<B_, 256>>>(w, conv_w, mod_w, mod_b);
    conv_mma_kernel<<<dim3(W_ / TW, H_, B_), 256, SMEM_TOTAL>>>(out);
    (void)in_sizes; (void)n_in; (void)out_size;
}

// round 15
// speedup vs baseline: 3.2809x; 1.1485x over previous
#include <cuda_runtime.h>
#include <cuda_bf16.h>
#include <cstdint>

// ---------------------------------------------------------------------------
// Shapes (fixed)
// ---------------------------------------------------------------------------
#define B_    4
#define CIN   64
#define COUT  64
#define H_    512
#define W_    512
#define WDIM  512
#define HW    (H_ * W_)

// conv tiling: block = 2 out-rows x 128 px, all 64 cout
#define TW    128
#define RR    2
#define PXW   130                     // staged px per row: [colbase-1, colbase+129)
#define ROWB  (PXW * 128)             // 16640 B per (row, comp)
#define COMPB (4 * ROWB)              // 66560 B: 4 rows, one comp
#define XBYTES (2 * COMPB)            // 133120 B
#define BKH   (6 * 2048 * 4)          // 49152 B: one kh (3 kw x 2 comp slices)
#define SMEM_TOTAL (XBYTES + 2 * BKH) // 231424 B

// x split bf16, transposed: [b][comp][h][w][cin]
__device__ __align__(16) __nv_bfloat16 g_xs[(size_t)B_ * 2 * HW * CIN];
// W fragments, per b: 18 slices (tap*2+comp) x 2048 u32 in HMMA-lane order
__device__ __align__(16) uint32_t g_wB[B_][18 * 2048];

// ---------------------------------------------------------------------------
// helpers
// ---------------------------------------------------------------------------
__device__ __forceinline__ uint32_t smem_u32(const void* p) {
    return (uint32_t)__cvta_generic_to_shared(p);
}
__device__ __forceinline__ void cp16(uint32_t dst, const void* src, bool pred) {
    int sz = pred ? 16 : 0;
    asm volatile("cp.async.cg.shared.global [%0], [%1], 16, %2;"
                 :: "r"(dst), "l"(src), "r"(sz));
}
__device__ __forceinline__ void cp_commit() { asm volatile("cp.async.commit_group;"); }
__device__ __forceinline__ void cp_wait0()  { asm volatile("cp.async.wait_group 0;"); }
__device__ __forceinline__ void cp_wait1()  { asm volatile("cp.async.wait_group 1;"); }

__device__ __forceinline__ void ldsm_x4(uint32_t* r, uint32_t addr) {
    asm volatile("ldmatrix.sync.aligned.m8n8.x4.shared.b16 {%0,%1,%2,%3}, [%4];"
                 : "=r"(r[0]), "=r"(r[1]), "=r"(r[2]), "=r"(r[3]) : "r"(addr));
}
__device__ __forceinline__ void mma16816(float* c, const uint32_t* a, const uint2 b) {
    asm volatile("mma.sync.aligned.m16n8k16.row.col.f32.bf16.bf16.f32 "
                 "{%0,%1,%2,%3}, {%4,%5,%6,%7}, {%8,%9}, {%0,%1,%2,%3};"
                 : "+f"(c[0]), "+f"(c[1]), "+f"(c[2]), "+f"(c[3])
                 : "r"(a[0]), "r"(a[1]), "r"(a[2]), "r"(a[3]),
                   "r"(b.x), "r"(b.y));
}

// ---------------------------------------------------------------------------
// Pre-pass: split x fp32 -> {hi, lo} bf16, transposed to [b][comp][h][w][cin].
// Grid (4 wchunks, 512 h, 4 b), 256 threads.
// smem tile swizzled: logical (cin, col) stored at phys col = col ^ (4*(cin>>3))
// -> read phase (lanes vary cg=cin>>3) hits 16 distinct banks, 2-way broadcast
// -> conflict-free (was 16-way conflicted).
// ---------------------------------------------------------------------------
__global__ void xsplit_kernel(const float* __restrict__ x) {
    __shared__ float s[64][128];
    const int tid = threadIdx.x;
    const int wc = blockIdx.x, h = blockIdx.y, b = blockIdx.z;

    // load tile [64 cin][128 w], float4, swizzled store (16B-chunk XOR)
    for (int i = tid; i < 2048; i += 256) {
        int cin = i >> 5, w4 = i & 31;
        float4 v = *(const float4*)(x + ((size_t)(b * 64 + cin) * HW)
                                     + h * 512 + wc * 128 + w4 * 4);
        ((float4*)s[cin])[w4 ^ (cin >> 3)] = v;
    }
    __syncthreads();

    // write [w][cin] bf16, per comp, uint4 (8 cins) at a time
    for (int i = tid; i < 2048; i += 256) {
        int w = i >> 4, comp = (i >> 3) & 1, cg = i & 7;
        uint32_t pk[4];
        #pragma unroll
        for (int j = 0; j < 4; ++j) {
            float v0 = s[cg * 8 + 2 * j][w ^ (4 * cg)];
            float v1 = s[cg * 8 + 2 * j + 1][w ^ (4 * cg)];
            __nv_bfloat16 h0 = __float2bfloat16(v0);
            __nv_bfloat16 h1 = __float2bfloat16(v1);
            if (comp) {
                h0 = __float2bfloat16(v0 - __bfloat162float(h0));
                h1 = __float2bfloat16(v1 - __bfloat162float(h1));
            }
            pk[j] = (uint32_t)__bfloat16_as_ushort(h0)
                  | ((uint32_t)__bfloat16_as_ushort(h1) << 16);
        }
        uint4* dst = (uint4*)(g_xs + (((size_t)(b * 2 + comp) * HW
                                       + h * 512 + wc * 128 + w) * 64 + cg * 8));
        *dst = make_uint4(pk[0], pk[1], pk[2], pk[3]);
    }
}

// ---------------------------------------------------------------------------
// prep: style/demod, then write folded split-bf16 weights in per-lane HMMA
// B-fragment order: word idx = (((tap*2+comp)*8+gna)*4+kstep)*64 + lane*2 + reg.
// conv_w layout [kh][kw][cin][cout]; B element (n=cout, k=cin).
// ---------------------------------------------------------------------------
__global__ void prep_kernel(const float* __restrict__ w,
                            const float* __restrict__ conv_w,
                            const float* __restrict__ mod_w,
                            const float* __restrict__ mod_b) {
    __shared__ float s_style[CIN];
    __shared__ float s_d[COUT];
    const int b   = blockIdx.x;
    const int tid = threadIdx.x;
    const float rc_dense = 0.04419417382415922f;  // 1/sqrt(512)
    const float rc_conv  = 1.0f / 24.0f;          // 1/sqrt(3*3*64)

    if (tid < CIN) {
        float s = 0.f;
        const float* wb = w + b * WDIM;
        #pragma unroll 8
        for (int d = 0; d < WDIM; ++d)
            s += wb[d] * mod_w[d * CIN + tid];
        s_style[tid] = s * rc_dense + mod_b[tid] + 1.0f;
    }
    __syncthreads();

    if (tid < COUT) {
        float ss = 0.f;
        for (int cin = 0; cin < CIN; ++cin) {
            float st = rc_conv * s_style[cin];
            #pragma unroll
            for (int tap = 0; tap < 9; ++tap) {
                float v = conv_w[(tap * CIN + cin) * COUT + tid] * st;
                ss += v * v;
            }
        }
        s_d[tid] = rsqrtf(ss + 1e-8f);
    }
    __syncthreads();

    uint32_t* dst = g_wB[b];
    for (int idx = tid; idx < 18 * 2048; idx += 256) {
        int slice = idx >> 11;           // tap*2 + comp
        int rem   = idx & 2047;
        int gna   = rem >> 8;            // 0..7
        int kstep = (rem >> 6) & 3;
        int lane  = (rem >> 1) & 31;
        int reg   = rem & 1;
        int tap = slice >> 1, comp = slice & 1;
        int n  = gna * 8 + (lane >> 2);
        int k0 = kstep * 16 + 2 * (lane & 3) + reg * 8;
        uint32_t word = 0;
        #pragma unroll
        for (int hh = 0; hh < 2; ++hh) {
            int k = k0 + hh;
            float wv = rc_conv * conv_w[(tap * CIN + k) * COUT + n]
                     * s_style[k] * s_d[n];
            __nv_bfloat16 hi = __float2bfloat16(wv);
            __nv_bfloat16 o  = comp ? __float2bfloat16(wv - __bfloat162float(hi))
                                    : hi;
            word |= (uint32_t)__bfloat16_as_ushort(o) << (16 * hh);
        }
        dst[idx] = word;
    }
}

// ---------------------------------------------------------------------------
// conv: split-bf16 implicit GEMM via mma.sync m16n8k16.
// Block = 2 out-rows x 128 px x 64 cout; 8 warps = 2(row) x 2(M:64px) x 2(N:32co).
// Stages ONCE per block: 4 input rows of [130px][64cin][2comp] (133 KB) and,
// per kh, 48 KB of lane-ordered B fragments into smem (double-buffered).
// cp.async groups: g0 = rows01+B0, g1 = rows23+B1, g2 = B2 (after kh0 drains
// buf0). Waits: kh0/kh1 -> wait_group 1, kh2 -> wait_group 0; sync after each.
// Cuts x DRAM 856->545 MB and B L2 2.4->0.6 GB vs the per-row variant.
// ---------------------------------------------------------------------------
__global__ void __launch_bounds__(256, 1)
conv_mma_kernel(float* __restrict__ out) {
    extern __shared__ char smem[];
    const uint32_t sb = smem_u32(smem);
    const int tid  = threadIdx.x;
    const int lane = tid & 31;
    const int wid  = tid >> 5;
    const int wn     = wid & 1;          // N offset = wn*32
    const int warp_m = (wid >> 1) & 1;   // M offset = warp_m*64
    const int warp_r = wid >> 2;         // out-row within block
    const int colbase = blockIdx.x * TW;
    const int rowbase = blockIdx.y * RR;
    const int b       = blockIdx.z;

    float acc[4][4][4];                  // [matom][natom][reg]
    #pragma unroll
    for (int i = 0; i < 4; ++i)
        #pragma unroll
        for (int j = 0; j < 4; ++j)
            #pragma unroll
            for (int r = 0; r < 4; ++r) acc[i][j][r] = 0.f;

    // stage one input row (both comps) into slot ri
    auto stage_row = [&](int ri, int ir) {
        for (int idx = tid; idx < 2 * PXW * 8; idx += 256) {
            int g    = idx & 7;
            int p    = (idx >> 3) % PXW;
            int comp = idx / (PXW * 8);
            int gpx  = colbase - 1 + p;
            bool ok  = ((unsigned)ir < (unsigned)H_) &&
                       ((unsigned)gpx < (unsigned)W_);
            const __nv_bfloat16* src =
                g_xs + ((size_t)(b * 2 + comp) * HW
                        + (ok ? (ir * 512 + gpx) : 0)) * 64 + g * 8;
            uint32_t dst = sb + (uint32_t)comp * COMPB + (uint32_t)ri * ROWB
                         + (uint32_t)p * 128 + (uint32_t)((g ^ (p & 7)) * 16);
            cp16(dst, src, ok);
        }
    };
    // stage all 6 B slices of one kh (linear 48 KB)
    auto stage_B = [&](int kh, int buf) {
        const uint32_t* src = g_wB[b] + kh * 6 * 2048;
        for (int i = tid; i < 3072; i += 256)
            cp16(sb + XBYTES + (uint32_t)buf * BKH + (uint32_t)i * 16,
                 src + i * 4, true);
    };

    stage_row(0, rowbase - 1); stage_row(1, rowbase);     stage_B(0, 0); cp_commit();
    stage_row(2, rowbase + 1); stage_row(3, rowbase + 2); stage_B(1, 1); cp_commit();

    const int pxe = ((lane >> 3) & 1) * 8 + (lane & 7);  // intra-mat px part
    const int kge = lane >> 4;                           // k-granule part

    #pragma unroll
    for (int kh = 0; kh < 3; ++kh) {
        if (kh < 2) cp_wait1(); else cp_wait0();
        __syncthreads();

        const int buf = (kh == 1) ? 1 : 0;
        const char* Bb = smem + XBYTES + buf * BKH;
        const uint32_t xrow = sb + (uint32_t)(warp_r + kh) * ROWB;

        #pragma unroll
        for (int kw = 0; kw < 3; ++kw) {
            #pragma unroll
            for (int kstep = 0; kstep < 4; ++kstep) {
                // ---- A fragments (hi, lo) via ldmatrix.x4 ----
                uint32_t ahi[4][4], alo[4][4];
                #pragma unroll
                for (int m = 0; m < 4; ++m) {
                    int pxb = warp_m * 64 + m * 16 + pxe + kw;
                    uint32_t a0 = xrow + (uint32_t)pxb * 128
                                + (uint32_t)(((kstep * 2 + kge) ^ (pxb & 7)) * 16);
                    ldsm_x4(ahi[m], a0);
                    ldsm_x4(alo[m], a0 + COMPB);
                }
                // ---- B fragments (hi, lo) lane-ordered LDS.64 ----
                uint2 bhi[4], blo[4];
                #pragma unroll
                for (int na = 0; na < 4; ++na) {
                    uint32_t off = (uint32_t)((kw * 2) * 8192
                                 + (((wn * 4 + na) * 4 + kstep) * 64 + lane * 2) * 4);
                    bhi[na] = *(const uint2*)(Bb + off);
                    blo[na] = *(const uint2*)(Bb + off + 8192);
                }
                // ---- hh + lh + hl ----
                #pragma unroll
                for (int m = 0; m < 4; ++m)
                    #pragma unroll
                    for (int na = 0; na < 4; ++na) {
                        mma16816(acc[m][na], ahi[m], bhi[na]);
                        mma16816(acc[m][na], alo[m], bhi[na]);
                        mma16816(acc[m][na], ahi[m], blo[na]);
                    }
            }
        }
        __syncthreads();                  // all warps done with buf before reuse
        if (kh == 0) { stage_B(2, 0); cp_commit(); }
    }

    // ---- epilogue: out[b][cout][orow][col] ----
    const int orow = rowbase + warp_r;
    #pragma unroll
    for (int m = 0; m < 4; ++m) {
        int px = colbase + warp_m * 64 + m * 16 + (lane >> 2);
        #pragma unroll
        for (int na = 0; na < 4; ++na) {
            int cout = wn * 32 + na * 8 + 2 * (lane & 3);
            float* o = out + ((size_t)(b * COUT + cout)) * HW
                     + (size_t)orow * W_ + px;
            o[0]      = acc[m][na][0];   // (px,   cout)
            o[HW]     = acc[m][na][1];   // (px,   cout+1)
            o[8]      = acc[m][na][2];   // (px+8, cout)
            o[HW + 8] = acc[m][na][3];   // (px+8, cout+1)
        }
    }
}

// ---------------------------------------------------------------------------
// Harness entry. Inputs (metadata order): x, w, conv_w, mod_w, mod_b.
// ---------------------------------------------------------------------------
extern "C" void kernel_launch(void* const* d_in, const int* in_sizes, int n_in,
                              void* d_out, int out_size) {
    const float* x      = (const float*)d_in[0];
    const float* w      = (const float*)d_in[1];
    const float* conv_w = (const float*)d_in[2];
    const float* mod_w  = (const float*)d_in[3];
    const float* mod_b  = (const float*)d_in[4];
    float* out = (float*)d_out;

    cudaFuncSetAttribute(conv_mma_kernel,
                         cudaFuncAttributeMaxDynamicSharedMemorySize, SMEM_TOTAL);
    xsplit_kernel<<<dim3(4, 512, B_), 256>>>(x);
    prep_kernel<<<B_, 256>>>(w, conv_w, mod_w, mod_b);
    conv_mma_kernel<<<dim3(W_ / TW, H_ / RR, B_), 256, SMEM_TOTAL>>>(out);
    (void)in_sizes; (void)n_in; (void)out_size;
}